// round 14
// baseline (speedup 1.0000x reference)
#include <cuda_runtime.h>
#include <cuda_fp16.h>
#include <math.h>

#define NN 50000
#define DD 128
#define EE 600000
#define ND ((size_t)NN * DD)
#define CAP 64                       // bucket capacity (Poisson(12), P(deg>=64)~1e-30)
#define NB ((NN + 255) / 256)

// Scratch (no cudaMalloc allowed): device globals.
__device__ float g_s[2][NN];         // gate projections, double-buffered by parity
__device__ float g_t[2][NN];
__device__ int g_cnt[NN];            // in-degree (counts up during build)
__device__ int g_bkt[NN * CAP];      // src node per slot, bucketed by dst
__device__ __half g_hf[2][NN * DD];  // fp16 feature mirror, double-buffered by parity
__device__ int g_is64;

__device__ __forceinline__ float warp_sum(float v) {
#pragma unroll
    for (int o = 16; o > 0; o >>= 1) v += __shfl_xor_sync(0xffffffffu, v, o);
    return v;
}

// Fast gate: sigmoid(selu(e)).
__device__ __forceinline__ float gate_alpha(float e0) {
    const float SC = 1.0507009873554804934193349852946f;
    const float AL = 1.6732632423543772848170429916717f;
    float u = e0 > 0.f ? SC * e0 : SC * AL * (__expf(e0) - 1.0f);
    return __fdividef(1.0f, 1.0f + __expf(-u));
}

// ---------------------------------------------------------------------------
// Launch 1: out[0] = l2norm(x) (fp32) + fp16 mirror (parity 0) + s/t parity-0
// projections. Housekeeping folded in: edge-dtype detect, g_cnt zeroing.
__global__ void norm_x_kernel(const float* __restrict__ x,
                              const float* __restrict__ w0,
                              float* __restrict__ out,
                              const int* __restrict__ ei32) {
    if (blockIdx.x == 0 && threadIdx.x == 0) {
        int all0 = 1;
#pragma unroll
        for (int i = 1; i < 129; i += 2) all0 &= (ei32[i] == 0);
        g_is64 = all0;
    }
    int zi = blockIdx.x * 256 + threadIdx.x;
    if (blockIdx.x < NB && zi < NN) g_cnt[zi] = 0;

    int row = (blockIdx.x * blockDim.x + threadIdx.x) >> 5;
    int lane = threadIdx.x & 31;
    if (row >= NN) return;

    float4 v = ((const float4*)(x + (size_t)row * DD))[lane];
    float ss = v.x * v.x + v.y * v.y + v.z * v.z + v.w * v.w;
    ss = warp_sum(ss);
    float inv = 1.0f / fmaxf(sqrtf(ss), 1e-12f);

    float4 o = make_float4(v.x * inv, v.y * inv, v.z * inv, v.w * inv);
    ((float4*)(out + (size_t)row * DD))[lane] = o;

    __half2 q0 = __floats2half2_rn(o.x, o.y);
    __half2 q1 = __floats2half2_rn(o.z, o.w);
    uint2 u;
    u.x = *(unsigned*)&q0;
    u.y = *(unsigned*)&q1;
    ((uint2*)(g_hf[0] + (size_t)row * DD))[lane] = u;

    float4 a = ((const float4*)w0)[lane];
    float4 b = ((const float4*)(w0 + DD))[lane];
    float sd = warp_sum(o.x * a.x + o.y * a.y + o.z * a.z + o.w * a.w);
    float td = warp_sum(o.x * b.x + o.y * b.y + o.z * b.z + o.w * b.w);
    if (lane == 0) { g_s[0][row] = sd; g_t[0][row] = td; }
}

// Launch 2: single-pass bucket build (unpack + scatter, no scan needed).
__global__ void build_kernel(const void* __restrict__ ei) {
    int e = blockIdx.x * blockDim.x + threadIdx.x;
    if (e >= EE) return;
    int s, d;
    if (g_is64) {
        const long long* p = (const long long*)ei;
        s = (int)p[e];
        d = (int)p[EE + e];
    } else {
        const int* p = (const int*)ei;
        s = p[e];
        d = p[EE + e];
    }
    int pos = atomicAdd(&g_cnt[d], 1);
    if (pos < CAP) g_bkt[d * CAP + pos] = s;
}

// ---------------------------------------------------------------------------
// Launches 3-5: fused hop, TWO warps per dst row (pair h=0,1).
// Slot interleave: warp h, lane j owns global slot G = 8*(j/4) + 4h + (j%4),
// so consecutive batches-of-4 alternate between the warps -> each warp runs
// ~half the serial L2 ladder. Gate computed in-warp for owned slots.
// Pair reduction via smem + bar.sync(1+pair, 64); warp 0 does the epilogue.
template <bool HAS_NEXT>
__global__ void hop_kernel(const float* __restrict__ bptr,
                           const float* __restrict__ noise_k,
                           const float* __restrict__ wk,
                           float* __restrict__ out,
                           int parity) {
    __shared__ float4 red[4][32];

    int gwarp = (blockIdx.x * blockDim.x + threadIdx.x) >> 5;  // 0..99999
    int row = gwarp >> 1;            // exact: 100000 warps for 50000 rows
    int h = gwarp & 1;
    int lane = threadIdx.x & 31;
    int pair = (threadIdx.x >> 6);   // 0..3 within block

    const float* sbuf = g_s[parity];
    const __half* hf = g_hf[parity];
    float tb = g_t[parity][row] + *bptr;

    int deg = min(g_cnt[row], CAP);
    const int* bkt = g_bkt + row * CAP;

    // Gate for my interleaved slots.
    int G = ((lane >> 2) << 3) + (h << 2) + (lane & 3);
    int sj = 0;
    float al = 0.f;
    if (G < deg) {
        sj = bkt[G];
        al = gate_alpha(sbuf[sj] + tb);
    }

    float4 acc = make_float4(0.f, 0.f, 0.f, 0.f);

    // Local batch k consumes lanes k..k+3 (global slots 8*(k/4)+4h ..+3).
    for (int k = 0; (((k >> 2) << 3) + (h << 2)) < deg; k += 4) {
        int s0 = __shfl_sync(0xffffffffu, sj, k);
        int s1 = __shfl_sync(0xffffffffu, sj, k + 1);
        int s2 = __shfl_sync(0xffffffffu, sj, k + 2);
        int s3 = __shfl_sync(0xffffffffu, sj, k + 3);
        float a0 = __shfl_sync(0xffffffffu, al, k);
        float a1 = __shfl_sync(0xffffffffu, al, k + 1);
        float a2 = __shfl_sync(0xffffffffu, al, k + 2);
        float a3 = __shfl_sync(0xffffffffu, al, k + 3);
        uint2 u0 = ((const uint2*)(hf + (size_t)s0 * DD))[lane];
        uint2 u1 = ((const uint2*)(hf + (size_t)s1 * DD))[lane];
        uint2 u2 = ((const uint2*)(hf + (size_t)s2 * DD))[lane];
        uint2 u3 = ((const uint2*)(hf + (size_t)s3 * DD))[lane];
        float2 p0 = __half22float2(*(__half2*)&u0.x);
        float2 p1 = __half22float2(*(__half2*)&u0.y);
        acc.x += a0 * p0.x; acc.y += a0 * p0.y;
        acc.z += a0 * p1.x; acc.w += a0 * p1.y;
        p0 = __half22float2(*(__half2*)&u1.x);
        p1 = __half22float2(*(__half2*)&u1.y);
        acc.x += a1 * p0.x; acc.y += a1 * p0.y;
        acc.z += a1 * p1.x; acc.w += a1 * p1.y;
        p0 = __half22float2(*(__half2*)&u2.x);
        p1 = __half22float2(*(__half2*)&u2.y);
        acc.x += a2 * p0.x; acc.y += a2 * p0.y;
        acc.z += a2 * p1.x; acc.w += a2 * p1.y;
        p0 = __half22float2(*(__half2*)&u3.x);
        p1 = __half22float2(*(__half2*)&u3.y);
        acc.x += a3 * p0.x; acc.y += a3 * p0.y;
        acc.z += a3 * p1.x; acc.w += a3 * p1.y;
    }

    // Pair reduction: warp 1 publishes, warp 0 combines + epilogue.
    if (h == 1) red[pair][lane] = acc;
    asm volatile("bar.sync %0, 64;" :: "r"(1 + pair) : "memory");
    if (h == 1) return;

    float4 p = red[pair][lane];
    acc.x += p.x; acc.y += p.y; acc.z += p.z; acc.w += p.w;

    float4 n = ((const float4*)(noise_k + (size_t)row * DD))[lane];
    acc.x += 0.1f * n.x; acc.y += 0.1f * n.y;
    acc.z += 0.1f * n.z; acc.w += 0.1f * n.w;

    float ss = acc.x * acc.x + acc.y * acc.y + acc.z * acc.z + acc.w * acc.w;
    ss = warp_sum(ss);
    float inv = 1.0f / fmaxf(sqrtf(ss), 1e-12f);

    float4 o = make_float4(acc.x * inv, acc.y * inv, acc.z * inv, acc.w * inv);
    ((float4*)(out + (size_t)row * DD))[lane] = o;

    if (HAS_NEXT) {
        int np = parity ^ 1;
        __half2 q0 = __floats2half2_rn(o.x, o.y);
        __half2 q1 = __floats2half2_rn(o.z, o.w);
        uint2 u;
        u.x = *(unsigned*)&q0;
        u.y = *(unsigned*)&q1;
        ((uint2*)(g_hf[np] + (size_t)row * DD))[lane] = u;

        float4 a = ((const float4*)wk)[lane];
        float4 b = ((const float4*)(wk + DD))[lane];
        float sd = warp_sum(o.x * a.x + o.y * a.y + o.z * a.z + o.w * a.w);
        float td = warp_sum(o.x * b.x + o.y * b.y + o.z * b.z + o.w * b.w);
        if (lane == 0) { g_s[np][row] = sd; g_t[np][row] = td; }
    }
}

// ---------------------------------------------------------------------------
extern "C" void kernel_launch(void* const* d_in, const int* in_sizes, int n_in,
                              void* d_out, int out_size) {
    const float* x = (const float*)d_in[0];
    const void* ei = d_in[1];
    const float* attn_w = (const float*)d_in[2];
    const float* attn_b = (const float*)d_in[3];
    const float* noise = (const float*)d_in[4];
    float* out = (float*)d_out;

    const int NORM_GRID = (NN + 7) / 8;     // warp per row
    const int HOP_GRID = (NN * 2) / 8;      // 2 warps per row: 12500 blocks
    const int E256 = (EE + 255) / 256;

    norm_x_kernel<<<NORM_GRID, 256>>>(x, attn_w, out, (const int*)ei);
    build_kernel<<<E256, 256>>>(ei);
    hop_kernel<true><<<HOP_GRID, 256>>>(attn_b + 0, noise,
                                        attn_w + 2 * DD, out + ND, 0);
    hop_kernel<true><<<HOP_GRID, 256>>>(attn_b + 1, noise + ND,
                                        attn_w + 4 * DD, out + 2 * ND, 1);
    hop_kernel<false><<<HOP_GRID, 256>>>(attn_b + 2, noise + 2 * ND,
                                         attn_w, out + 3 * ND, 0);
}

// round 15
// speedup vs baseline: 1.6798x; 1.6798x over previous
#include <cuda_runtime.h>
#include <cuda_fp16.h>
#include <math.h>

#define NN 50000
#define DD 128
#define EE 600000
#define ND ((size_t)NN * DD)
#define CAP 64                       // bucket capacity (Poisson(12), P(deg>=64)~1e-30)
#define NB ((NN + 255) / 256)

// Scratch (no cudaMalloc allowed): device globals.
__device__ float g_s[2][NN];         // gate projections, double-buffered by parity
__device__ float g_t[2][NN];
__device__ int g_cnt[NN];            // in-degree (counts up during build)
__device__ int g_bkt[NN * CAP];      // src node per slot, bucketed by dst
__device__ __half g_hf[2][NN * DD];  // fp16 feature mirror, double-buffered by parity
__device__ int g_is64;

__device__ __forceinline__ float warp_sum(float v) {
#pragma unroll
    for (int o = 16; o > 0; o >>= 1) v += __shfl_xor_sync(0xffffffffu, v, o);
    return v;
}

// Fast gate: sigmoid(selu(e)).
__device__ __forceinline__ float gate_alpha(float e0) {
    const float SC = 1.0507009873554804934193349852946f;
    const float AL = 1.6732632423543772848170429916717f;
    float u = e0 > 0.f ? SC * e0 : SC * AL * (__expf(e0) - 1.0f);
    return __fdividef(1.0f, 1.0f + __expf(-u));
}

// ---------------------------------------------------------------------------
// Launch 1: out[0] = l2norm(x) (fp32) + fp16 mirror (parity 0) + s/t parity-0
// projections. Housekeeping folded in: edge-dtype detect, g_cnt zeroing.
__global__ void norm_x_kernel(const float* __restrict__ x,
                              const float* __restrict__ w0,
                              float* __restrict__ out,
                              const int* __restrict__ ei32) {
    if (blockIdx.x == 0 && threadIdx.x == 0) {
        int all0 = 1;
#pragma unroll
        for (int i = 1; i < 129; i += 2) all0 &= (ei32[i] == 0);
        g_is64 = all0;
    }
    int zi = blockIdx.x * 256 + threadIdx.x;
    if (blockIdx.x < NB && zi < NN) g_cnt[zi] = 0;

    int row = (blockIdx.x * blockDim.x + threadIdx.x) >> 5;
    int lane = threadIdx.x & 31;
    if (row >= NN) return;

    float4 v = ((const float4*)(x + (size_t)row * DD))[lane];
    float ss = v.x * v.x + v.y * v.y + v.z * v.z + v.w * v.w;
    ss = warp_sum(ss);
    float inv = 1.0f / fmaxf(sqrtf(ss), 1e-12f);

    float4 o = make_float4(v.x * inv, v.y * inv, v.z * inv, v.w * inv);
    ((float4*)(out + (size_t)row * DD))[lane] = o;

    __half2 q0 = __floats2half2_rn(o.x, o.y);
    __half2 q1 = __floats2half2_rn(o.z, o.w);
    uint2 u;
    u.x = *(unsigned*)&q0;
    u.y = *(unsigned*)&q1;
    ((uint2*)(g_hf[0] + (size_t)row * DD))[lane] = u;

    float4 a = ((const float4*)w0)[lane];
    float4 b = ((const float4*)(w0 + DD))[lane];
    float sd = warp_sum(o.x * a.x + o.y * a.y + o.z * a.z + o.w * a.w);
    float td = warp_sum(o.x * b.x + o.y * b.y + o.z * b.z + o.w * b.w);
    if (lane == 0) { g_s[0][row] = sd; g_t[0][row] = td; }
}

// Launch 2: single-pass bucket build (unpack + scatter, no scan needed).
__global__ void build_kernel(const void* __restrict__ ei) {
    int e = blockIdx.x * blockDim.x + threadIdx.x;
    if (e >= EE) return;
    int s, d;
    if (g_is64) {
        const long long* p = (const long long*)ei;
        s = (int)p[e];
        d = (int)p[EE + e];
    } else {
        const int* p = (const int*)ei;
        s = p[e];
        d = p[EE + e];
    }
    int pos = atomicAdd(&g_cnt[d], 1);
    if (pos < CAP) g_bkt[d * CAP + pos] = s;
}

// ---------------------------------------------------------------------------
// Launches 3-5: fused hop, TWO warps per dst row (pair h=0,1).
// Warp h, lane j owns global slot G = 8*(j/4) + 4h + (j%4): consecutive
// batches-of-4 alternate between the pair's warps -> each warp runs ~half the
// serial L2 ladder. Pair combine via smem + ONE block-wide __syncthreads()
// (no named barriers -> no HW-barrier occupancy cap, the R14 failure).
template <bool HAS_NEXT>
__global__ void hop_kernel(const float* __restrict__ bptr,
                           const float* __restrict__ noise_k,
                           const float* __restrict__ wk,
                           float* __restrict__ out,
                           int parity) {
    __shared__ float4 red[4][32];

    int gwarp = (blockIdx.x * blockDim.x + threadIdx.x) >> 5;  // 0..99999 exact
    int row = gwarp >> 1;
    int h = gwarp & 1;
    int lane = threadIdx.x & 31;
    int pair = (threadIdx.x >> 6);   // 0..3 within block

    const float* sbuf = g_s[parity];
    const __half* hf = g_hf[parity];
    float tb = g_t[parity][row] + *bptr;

    int deg = min(g_cnt[row], CAP);
    const int* bkt = g_bkt + row * CAP;

    // Gate for my interleaved slots.
    int G = ((lane >> 2) << 3) + (h << 2) + (lane & 3);
    int sj = 0;
    float al = 0.f;
    if (G < deg) {
        sj = bkt[G];
        al = gate_alpha(sbuf[sj] + tb);
    }

    float4 acc = make_float4(0.f, 0.f, 0.f, 0.f);

    // Local batch k consumes lanes k..k+3 (global slots 8*(k/4)+4h ..+3).
    for (int k = 0; (((k >> 2) << 3) + (h << 2)) < deg; k += 4) {
        int s0 = __shfl_sync(0xffffffffu, sj, k);
        int s1 = __shfl_sync(0xffffffffu, sj, k + 1);
        int s2 = __shfl_sync(0xffffffffu, sj, k + 2);
        int s3 = __shfl_sync(0xffffffffu, sj, k + 3);
        float a0 = __shfl_sync(0xffffffffu, al, k);
        float a1 = __shfl_sync(0xffffffffu, al, k + 1);
        float a2 = __shfl_sync(0xffffffffu, al, k + 2);
        float a3 = __shfl_sync(0xffffffffu, al, k + 3);
        uint2 u0 = ((const uint2*)(hf + (size_t)s0 * DD))[lane];
        uint2 u1 = ((const uint2*)(hf + (size_t)s1 * DD))[lane];
        uint2 u2 = ((const uint2*)(hf + (size_t)s2 * DD))[lane];
        uint2 u3 = ((const uint2*)(hf + (size_t)s3 * DD))[lane];
        float2 p0 = __half22float2(*(__half2*)&u0.x);
        float2 p1 = __half22float2(*(__half2*)&u0.y);
        acc.x += a0 * p0.x; acc.y += a0 * p0.y;
        acc.z += a0 * p1.x; acc.w += a0 * p1.y;
        p0 = __half22float2(*(__half2*)&u1.x);
        p1 = __half22float2(*(__half2*)&u1.y);
        acc.x += a1 * p0.x; acc.y += a1 * p0.y;
        acc.z += a1 * p1.x; acc.w += a1 * p1.y;
        p0 = __half22float2(*(__half2*)&u2.x);
        p1 = __half22float2(*(__half2*)&u2.y);
        acc.x += a2 * p0.x; acc.y += a2 * p0.y;
        acc.z += a2 * p1.x; acc.w += a2 * p1.y;
        p0 = __half22float2(*(__half2*)&u3.x);
        p1 = __half22float2(*(__half2*)&u3.y);
        acc.x += a3 * p0.x; acc.y += a3 * p0.y;
        acc.z += a3 * p1.x; acc.w += a3 * p1.y;
    }

    // Pair combine: warp h=1 publishes, block syncs once, h=0 does epilogue.
    if (h == 1) red[pair][lane] = acc;
    __syncthreads();
    if (h == 1) return;

    float4 p = red[pair][lane];
    acc.x += p.x; acc.y += p.y; acc.z += p.z; acc.w += p.w;

    float4 n = ((const float4*)(noise_k + (size_t)row * DD))[lane];
    acc.x += 0.1f * n.x; acc.y += 0.1f * n.y;
    acc.z += 0.1f * n.z; acc.w += 0.1f * n.w;

    float ss = acc.x * acc.x + acc.y * acc.y + acc.z * acc.z + acc.w * acc.w;
    ss = warp_sum(ss);
    float inv = 1.0f / fmaxf(sqrtf(ss), 1e-12f);

    float4 o = make_float4(acc.x * inv, acc.y * inv, acc.z * inv, acc.w * inv);
    ((float4*)(out + (size_t)row * DD))[lane] = o;

    if (HAS_NEXT) {
        int np = parity ^ 1;
        __half2 q0 = __floats2half2_rn(o.x, o.y);
        __half2 q1 = __floats2half2_rn(o.z, o.w);
        uint2 u;
        u.x = *(unsigned*)&q0;
        u.y = *(unsigned*)&q1;
        ((uint2*)(g_hf[np] + (size_t)row * DD))[lane] = u;

        float4 a = ((const float4*)wk)[lane];
        float4 b = ((const float4*)(wk + DD))[lane];
        float sd = warp_sum(o.x * a.x + o.y * a.y + o.z * a.z + o.w * a.w);
        float td = warp_sum(o.x * b.x + o.y * b.y + o.z * b.z + o.w * b.w);
        if (lane == 0) { g_s[np][row] = sd; g_t[np][row] = td; }
    }
}

// ---------------------------------------------------------------------------
extern "C" void kernel_launch(void* const* d_in, const int* in_sizes, int n_in,
                              void* d_out, int out_size) {
    const float* x = (const float*)d_in[0];
    const void* ei = d_in[1];
    const float* attn_w = (const float*)d_in[2];
    const float* attn_b = (const float*)d_in[3];
    const float* noise = (const float*)d_in[4];
    float* out = (float*)d_out;

    const int NORM_GRID = (NN + 7) / 8;     // warp per row
    const int HOP_GRID = (NN * 2) / 8;      // 2 warps per row: 12500 blocks
    const int E256 = (EE + 255) / 256;

    norm_x_kernel<<<NORM_GRID, 256>>>(x, attn_w, out, (const int*)ei);
    build_kernel<<<E256, 256>>>(ei);
    hop_kernel<true><<<HOP_GRID, 256>>>(attn_b + 0, noise,
                                        attn_w + 2 * DD, out + ND, 0);
    hop_kernel<true><<<HOP_GRID, 256>>>(attn_b + 1, noise + ND,
                                        attn_w + 4 * DD, out + 2 * ND, 1);
    hop_kernel<false><<<HOP_GRID, 256>>>(attn_b + 2, noise + 2 * ND,
                                         attn_w, out + 3 * ND, 0);
}

// round 16
// speedup vs baseline: 1.6878x; 1.0048x over previous
#include <cuda_runtime.h>
#include <cuda_fp16.h>
#include <math.h>

#define NN 50000
#define DD 128
#define EE 600000
#define ND ((size_t)NN * DD)
#define CAP 64                       // bucket capacity (Poisson(12), P(deg>=64)~1e-30)

// Scratch (no cudaMalloc allowed): device globals.
__device__ float g_s[2][NN];         // gate projections, double-buffered by parity
__device__ float g_t[2][NN];
__device__ int g_cnt[NN];            // in-degree; zero-init at load, re-zeroed by last hop
__device__ int g_bkt[NN * CAP];      // src node per slot, bucketed by dst
__device__ __half g_hf[2][NN * DD];  // fp16 feature mirror, double-buffered by parity
__device__ int g_is64;

__device__ __forceinline__ float warp_sum(float v) {
#pragma unroll
    for (int o = 16; o > 0; o >>= 1) v += __shfl_xor_sync(0xffffffffu, v, o);
    return v;
}

// Fast gate: sigmoid(selu(e)).
__device__ __forceinline__ float gate_alpha(float e0) {
    const float SC = 1.0507009873554804934193349852946f;
    const float AL = 1.6732632423543772848170429916717f;
    float u = e0 > 0.f ? SC * e0 : SC * AL * (__expf(e0) - 1.0f);
    return __fdividef(1.0f, 1.0f + __expf(-u));
}

// ---------------------------------------------------------------------------
// Launch 1: bucket build. Self-detects edge dtype: int64 little-endian with
// values < 50000 => the first 8 odd int32 slots are all zero (prob of false
// positive for an int32 stream ~ (1/50000)^8). One L1-hot line, ~free.
// g_cnt is zero on entry: static init on first run, last-hop reset afterwards.
__global__ void build_kernel(const void* __restrict__ ei) {
    int e = blockIdx.x * blockDim.x + threadIdx.x;
    if (e >= EE) return;
    const int* p32 = (const int*)ei;
    bool is64 = (p32[1] == 0) & (p32[3] == 0) & (p32[5] == 0) & (p32[7] == 0) &
                (p32[9] == 0) & (p32[11] == 0) & (p32[13] == 0) & (p32[15] == 0);
    int s, d;
    if (is64) {
        const long long* p = (const long long*)ei;
        s = (int)p[e];
        d = (int)p[EE + e];
    } else {
        s = p32[e];
        d = p32[EE + e];
    }
    int pos = atomicAdd(&g_cnt[d], 1);
    if (pos < CAP) g_bkt[d * CAP + pos] = s;
}

// ---------------------------------------------------------------------------
// Launch 2: out[0] = l2norm(x) (fp32) + fp16 mirror (parity 0) + s/t parity-0.
__global__ void norm_x_kernel(const float* __restrict__ x,
                              const float* __restrict__ w0,
                              float* __restrict__ out) {
    int row = (blockIdx.x * blockDim.x + threadIdx.x) >> 5;
    int lane = threadIdx.x & 31;
    if (row >= NN) return;

    float4 v = __ldcs((const float4*)(x + (size_t)row * DD) + lane);
    float ss = v.x * v.x + v.y * v.y + v.z * v.z + v.w * v.w;
    ss = warp_sum(ss);
    float inv = 1.0f / fmaxf(sqrtf(ss), 1e-12f);

    float4 o = make_float4(v.x * inv, v.y * inv, v.z * inv, v.w * inv);
    __stcs((float4*)(out + (size_t)row * DD) + lane, o);

    __half2 q0 = __floats2half2_rn(o.x, o.y);
    __half2 q1 = __floats2half2_rn(o.z, o.w);
    uint2 u;
    u.x = *(unsigned*)&q0;
    u.y = *(unsigned*)&q1;
    ((uint2*)(g_hf[0] + (size_t)row * DD))[lane] = u;

    float4 a = ((const float4*)w0)[lane];
    float4 b = ((const float4*)(w0 + DD))[lane];
    float sd = warp_sum(o.x * a.x + o.y * a.y + o.z * a.z + o.w * a.w);
    float td = warp_sum(o.x * b.x + o.y * b.y + o.z * b.z + o.w * b.w);
    if (lane == 0) { g_s[0][row] = sd; g_t[0][row] = td; }
}

// ---------------------------------------------------------------------------
// Launches 3-5: fused hop, warp per dst row (R9 structure: 32 regs, occ ~81%).
// Gate phase: lanes 0..deg-1 compute alphas in parallel; padding lanes carry
// alpha=0, src=0 (row 0 stays L1-hot, contributes 0).
// Gather phase: batch-4 pipeline of __ldg 256B row gathers.
// Streaming traffic (noise/out) uses evict-first hints to keep L1 for gathers.
// The last hop (HAS_NEXT=false) resets g_cnt[row]=0 for the next replay.
template <bool HAS_NEXT>
__global__ void hop_kernel(const float* __restrict__ bptr,
                           const float* __restrict__ noise_k,
                           const float* __restrict__ wk,
                           float* __restrict__ out,
                           int parity) {
    int row = (blockIdx.x * blockDim.x + threadIdx.x) >> 5;
    int lane = threadIdx.x & 31;
    if (row >= NN) return;

    const float* sbuf = g_s[parity];
    const __half* hf = g_hf[parity];
    float tb = g_t[parity][row] + *bptr;

    int deg = min(g_cnt[row], CAP);
    if (!HAS_NEXT) {
        if (lane == 0) g_cnt[row] = 0;   // consume: zero for next replay
    }
    const int* bkt = g_bkt + row * CAP;

    float4 acc = make_float4(0.f, 0.f, 0.f, 0.f);

    for (int base = 0; base < deg; base += 32) {
        int j = base + lane;
        int sj = 0;
        float al = 0.f;
        if (j < deg) {
            sj = bkt[j];
            al = gate_alpha(sbuf[sj] + tb);
        }
        int cnt = min(32, deg - base);
        int cnt4 = (cnt + 3) & ~3;          // round up; padding lanes have al=0
        for (int k = 0; k < cnt4; k += 4) {
            int s0 = __shfl_sync(0xffffffffu, sj, k);
            int s1 = __shfl_sync(0xffffffffu, sj, k + 1);
            int s2 = __shfl_sync(0xffffffffu, sj, k + 2);
            int s3 = __shfl_sync(0xffffffffu, sj, k + 3);
            float a0 = __shfl_sync(0xffffffffu, al, k);
            float a1 = __shfl_sync(0xffffffffu, al, k + 1);
            float a2 = __shfl_sync(0xffffffffu, al, k + 2);
            float a3 = __shfl_sync(0xffffffffu, al, k + 3);
            uint2 u0 = __ldg((const uint2*)(hf + (size_t)s0 * DD) + lane);
            uint2 u1 = __ldg((const uint2*)(hf + (size_t)s1 * DD) + lane);
            uint2 u2 = __ldg((const uint2*)(hf + (size_t)s2 * DD) + lane);
            uint2 u3 = __ldg((const uint2*)(hf + (size_t)s3 * DD) + lane);
            float2 p0 = __half22float2(*(__half2*)&u0.x);
            float2 p1 = __half22float2(*(__half2*)&u0.y);
            acc.x += a0 * p0.x; acc.y += a0 * p0.y;
            acc.z += a0 * p1.x; acc.w += a0 * p1.y;
            p0 = __half22float2(*(__half2*)&u1.x);
            p1 = __half22float2(*(__half2*)&u1.y);
            acc.x += a1 * p0.x; acc.y += a1 * p0.y;
            acc.z += a1 * p1.x; acc.w += a1 * p1.y;
            p0 = __half22float2(*(__half2*)&u2.x);
            p1 = __half22float2(*(__half2*)&u2.y);
            acc.x += a2 * p0.x; acc.y += a2 * p0.y;
            acc.z += a2 * p1.x; acc.w += a2 * p1.y;
            p0 = __half22float2(*(__half2*)&u3.x);
            p1 = __half22float2(*(__half2*)&u3.y);
            acc.x += a3 * p0.x; acc.y += a3 * p0.y;
            acc.z += a3 * p1.x; acc.w += a3 * p1.y;
        }
    }

    float4 n = __ldcs((const float4*)(noise_k + (size_t)row * DD) + lane);
    acc.x += 0.1f * n.x; acc.y += 0.1f * n.y;
    acc.z += 0.1f * n.z; acc.w += 0.1f * n.w;

    float ss = acc.x * acc.x + acc.y * acc.y + acc.z * acc.z + acc.w * acc.w;
    ss = warp_sum(ss);
    float inv = 1.0f / fmaxf(sqrtf(ss), 1e-12f);

    float4 o = make_float4(acc.x * inv, acc.y * inv, acc.z * inv, acc.w * inv);
    __stcs((float4*)(out + (size_t)row * DD) + lane, o);

    if (HAS_NEXT) {
        int np = parity ^ 1;
        __half2 q0 = __floats2half2_rn(o.x, o.y);
        __half2 q1 = __floats2half2_rn(o.z, o.w);
        uint2 u;
        u.x = *(unsigned*)&q0;
        u.y = *(unsigned*)&q1;
        ((uint2*)(g_hf[np] + (size_t)row * DD))[lane] = u;

        float4 a = ((const float4*)wk)[lane];
        float4 b = ((const float4*)(wk + DD))[lane];
        float sd = warp_sum(o.x * a.x + o.y * a.y + o.z * a.z + o.w * a.w);
        float td = warp_sum(o.x * b.x + o.y * b.y + o.z * b.z + o.w * b.w);
        if (lane == 0) { g_s[np][row] = sd; g_t[np][row] = td; }
    }
}

// ---------------------------------------------------------------------------
extern "C" void kernel_launch(void* const* d_in, const int* in_sizes, int n_in,
                              void* d_out, int out_size) {
    const float* x = (const float*)d_in[0];
    const void* ei = d_in[1];
    const float* attn_w = (const float*)d_in[2];
    const float* attn_b = (const float*)d_in[3];
    const float* noise = (const float*)d_in[4];
    float* out = (float*)d_out;

    const int NORM_GRID = (NN + 7) / 8;   // warp per row, 256-thread blocks
    const int E256 = (EE + 255) / 256;

    build_kernel<<<E256, 256>>>(ei);                       // g_cnt zero on entry
    norm_x_kernel<<<NORM_GRID, 256>>>(x, attn_w, out);
    hop_kernel<true><<<NORM_GRID, 256>>>(attn_b + 0, noise,
                                         attn_w + 2 * DD, out + ND, 0);
    hop_kernel<true><<<NORM_GRID, 256>>>(attn_b + 1, noise + ND,
                                         attn_w + 4 * DD, out + 2 * ND, 1);
    hop_kernel<false><<<NORM_GRID, 256>>>(attn_b + 2, noise + 2 * ND,
                                          attn_w, out + 3 * ND, 0);   // resets g_cnt
}